// round 13
// baseline (speedup 1.0000x reference)
#include <cuda_runtime.h>
#include <cstdint>

#define BB 1024
#define TT 512
#define II 64
#define HH 32

typedef unsigned long long ull;

// Scratch: x_proj with b_ih+b_hh folded in, layout [b][t][k]  (64 MB)
__device__ float g_xp[(size_t)BB * TT * HH];

// ---------- packed f32x2 helpers ----------
__device__ __forceinline__ ull pk(float lo, float hi) {
    ull r; asm("mov.b64 %0, {%1,%2};" : "=l"(r) : "f"(lo), "f"(hi)); return r;
}
__device__ __forceinline__ float2 upk(ull v) {
    float2 f; asm("mov.b64 {%0,%1}, %2;" : "=f"(f.x), "=f"(f.y) : "l"(v)); return f;
}
__device__ __forceinline__ ull fma2(ull a, ull b, ull c) {
    ull d; asm("fma.rn.f32x2 %0, %1, %2, %3;" : "=l"(d) : "l"(a), "l"(b), "l"(c)); return d;
}
__device__ __forceinline__ ull mul2(ull a, ull b) {
    ull d; asm("mul.rn.f32x2 %0, %1, %2;" : "=l"(d) : "l"(a), "l"(b)); return d;
}
__device__ __forceinline__ ull add2(ull a, ull b) {
    ull d; asm("add.rn.f32x2 %0, %1, %2;" : "=l"(d) : "l"(a), "l"(b)); return d;
}

// Fast exact tanh: 1 - 2/(exp(2x)+1). Saturates correctly at +/-1, no NaN.
__device__ __forceinline__ float ftanh(float x) {
    float e = __expf(2.0f * x);
    return 1.0f - __fdividef(2.0f, e + 1.0f);
}

__device__ __forceinline__ void pair_bar(int pairid) {
    asm volatile("bar.sync %0, 64;" :: "r"(pairid + 1) : "memory");
}

// =====================================================================
// Kernel 1: x_proj (register-direct, double-buffered x prefetch).
// 256 threads/block (2 warps per SMSP for latency overlap), 2 rows/thread.
// =====================================================================
__global__ __launch_bounds__(256) void xproj_kernel(
    const float* __restrict__ x, const float* __restrict__ W_ih,
    const float* __restrict__ b_ih, const float* __restrict__ b_hh)
{
    __shared__ ull wT[II * 16];      // [i][kp] = {W[2kp][i], W[2kp+1][i]}   8 KB
    __shared__ ull bias2[16];
    const int tid = threadIdx.x;

    #pragma unroll
    for (int r = 0; r < 4; r++) {
        int e = tid + r * 256;                 // e = i*16 + kp
        int i = e >> 4, kp = e & 15;
        wT[e] = pk(W_ih[(2 * kp) * II + i], W_ih[(2 * kp + 1) * II + i]);
    }
    if (tid < 16)
        bias2[tid] = pk(b_ih[2 * tid] + b_hh[2 * tid],
                        b_ih[2 * tid + 1] + b_hh[2 * tid + 1]);
    __syncthreads();

    const size_t row0 = (size_t)blockIdx.x * 512 + tid * 2;
    const float4* xr0 = (const float4*)(x + row0 * II);
    const float4* xr1 = (const float4*)(x + (row0 + 1) * II);

    ull acc0[16], acc1[16];
    #pragma unroll
    for (int kp = 0; kp < 16; kp++) { ull b = bias2[kp]; acc0[kp] = b; acc1[kp] = b; }

    float4 bufA[2][4], bufB[2][4];
    #pragma unroll
    for (int u = 0; u < 4; u++) { bufA[0][u] = xr0[u]; bufB[0][u] = xr1[u]; }

    #pragma unroll
    for (int ic = 0; ic < 4; ic++) {
        const int cu = ic & 1;
        if (ic < 3) {
            #pragma unroll
            for (int u = 0; u < 4; u++) {
                bufA[cu ^ 1][u] = xr0[(ic + 1) * 4 + u];
                bufB[cu ^ 1][u] = xr1[(ic + 1) * 4 + u];
            }
        }
        const float* fa = (const float*)bufA[cu];
        const float* fb = (const float*)bufB[cu];
        #pragma unroll
        for (int ii = 0; ii < 16; ii++) {
            const int i = ic * 16 + ii;
            const ull xd0 = pk(fa[ii], fa[ii]);
            const ull xd1 = pk(fb[ii], fb[ii]);
            const ulonglong2* wrow = (const ulonglong2*)(wT + i * 16);
            #pragma unroll
            for (int kq = 0; kq < 8; kq++) {
                ulonglong2 w2 = wrow[kq];      // broadcast LDS.128
                acc0[2 * kq]     = fma2(w2.x, xd0, acc0[2 * kq]);
                acc0[2 * kq + 1] = fma2(w2.y, xd0, acc0[2 * kq + 1]);
                acc1[2 * kq]     = fma2(w2.x, xd1, acc1[2 * kq]);
                acc1[2 * kq + 1] = fma2(w2.y, xd1, acc1[2 * kq + 1]);
            }
        }
    }

    ulonglong2* o0 = (ulonglong2*)(g_xp + row0 * HH);
    ulonglong2* o1 = (ulonglong2*)(g_xp + (row0 + 1) * HH);
    #pragma unroll
    for (int kq = 0; kq < 8; kq++) {
        o0[kq] = make_ulonglong2(acc0[2 * kq], acc0[2 * kq + 1]);
        o1[kq] = make_ulonglong2(acc1[2 * kq], acc1[2 * kq + 1]);
    }
}

// =====================================================================
// Kernel 2: recurrence. 128-thread blocks = 2 producer/consumer pairs,
// 4 batches per pair (TWO independent f32x2 chains per producer warp:
// chain A = {b0,b1}, chain B = {b2,b3} -> their latency shadows overlap).
// Producers = warps 0,1 (SMSP 0,1); consumers = warps 2,3 (SMSP 2,3).
// Per-pair named barrier (bar.sync pair+1, 64), chunk = 8 steps.
// =====================================================================
__global__ __launch_bounds__(128) void rnn_kernel(
    const float* __restrict__ h0, const float* __restrict__ W_hh,
    const float* __restrict__ W_out, const float* __restrict__ b_out,
    float* __restrict__ out, int write_hlast)
{
    #define CK 8
    #define NC (TT / CK)                           // 64 chunks
    __shared__ ulonglong2 xb[2][2][CK * 32];       // [pair][par][tc*32+k] = {pk(b0,b1), pk(b2,b3)}
    __shared__ ulonglong2 pbuf[2][2][32 * (CK + 1)]; // [pair][par][k*9+tc] = {wo*hA2, wo*hB2}
    __shared__ ulonglong2 hbuf[2][2][HH];          // [pair][phase][k] = {hA2, hB2}

    const int wid  = threadIdx.x >> 5;
    const int lane = threadIdx.x & 31;
    const int pair = wid & 1;
    const int b0 = blockIdx.x * 8 + pair * 4;
    const ull z = pk(0.0f, 0.0f);

    if (wid < 2) {
        // ---------------- producer warp: two independent chains ----------------
        const int k = lane;
        ull wp2[HH];
        #pragma unroll
        for (int j = 0; j < HH; j++) { float w = W_hh[k * HH + j]; wp2[j] = pk(w, w); }
        const float wo = W_out[k];
        const ull wop = pk(wo, wo);

        float hA0 = h0[(b0 + 0) * HH + k], hA1 = h0[(b0 + 1) * HH + k];
        float hB0 = h0[(b0 + 2) * HH + k], hB1 = h0[(b0 + 3) * HH + k];
        hbuf[pair][0][k] = make_ulonglong2(pk(hA0, hA1), pk(hB0, hB1));

        for (int c = 0; c < NC; c++) {
            pair_bar(pair);                        // xb[pair][c&1] ready, pbuf free
            const ulonglong2* xq = xb[pair][c & 1];
            ulonglong2* pq = pbuf[pair][c & 1];
            #pragma unroll
            for (int tc = 0; tc < CK; tc++) {
                const int ph = tc & 1;
                ulonglong2 xv = xq[tc * 32 + k];   // LDS.128, off the h chain
                ull aA0 = xv.x, aA1 = z, aA2 = z, aA3 = z;
                ull aB0 = xv.y, aB1 = z, aB2 = z, aB3 = z;
                const ulonglong2* hb2 = hbuf[pair][ph];
                #pragma unroll
                for (int j = 0; j < HH; j += 4) {
                    ulonglong2 h0v = hb2[j];
                    aA0 = fma2(wp2[j], h0v.x, aA0);
                    aB0 = fma2(wp2[j], h0v.y, aB0);
                    ulonglong2 h1v = hb2[j + 1];
                    aA1 = fma2(wp2[j + 1], h1v.x, aA1);
                    aB1 = fma2(wp2[j + 1], h1v.y, aB1);
                    ulonglong2 h2v = hb2[j + 2];
                    aA2 = fma2(wp2[j + 2], h2v.x, aA2);
                    aB2 = fma2(wp2[j + 2], h2v.y, aB2);
                    ulonglong2 h3v = hb2[j + 3];
                    aA3 = fma2(wp2[j + 3], h3v.x, aA3);
                    aB3 = fma2(wp2[j + 3], h3v.y, aB3);
                }
                ull sA = add2(add2(aA0, aA1), add2(aA2, aA3));
                ull sB = add2(add2(aB0, aB1), add2(aB2, aB3));
                float2 fA = upk(sA), fB = upk(sB);
                hA0 = ftanh(fA.x); hA1 = ftanh(fA.y);
                hB0 = ftanh(fB.x); hB1 = ftanh(fB.y);
                ulonglong2 hn = make_ulonglong2(pk(hA0, hA1), pk(hB0, hB1));
                hbuf[pair][ph ^ 1][k] = hn;        // STS.128
                __syncwarp();
                pq[k * (CK + 1) + tc] =
                    make_ulonglong2(mul2(wop, hn.x), mul2(wop, hn.y));  // off-chain
            }
        }
        pair_bar(pair);                            // final pbuf chunk visible
        if (write_hlast) {
            float* hl = out + (size_t)BB * TT;
            hl[(b0 + 0) * HH + k] = hA0;
            hl[(b0 + 1) * HH + k] = hA1;
            hl[(b0 + 2) * HH + k] = hB0;
            hl[(b0 + 3) * HH + k] = hB1;
        }
    } else {
        // ---------------- consumer warp ----------------
        const int l = lane;
        const float bo = b_out[0];
        const float4* s0 = (const float4*)(g_xp + (size_t)(b0 + 0) * TT * HH);
        const float4* s1 = (const float4*)(g_xp + (size_t)(b0 + 1) * TT * HH);
        const float4* s2 = (const float4*)(g_xp + (size_t)(b0 + 2) * TT * HH);
        const float4* s3 = (const float4*)(g_xp + (size_t)(b0 + 3) * TT * HH);

        // chunk loader: 4 KB -> xb[pair][par]
        auto loadx = [&](int c) {
            const int off = c * (CK * HH / 4);
            ulonglong2* dst = xb[pair][c & 1];
            #pragma unroll
            for (int u = 0; u < 2; u++) {
                int e = u * 32 + l;                // float4 index 0..63
                float4 v0 = s0[off + e];
                float4 v1 = s1[off + e];
                float4 v2 = s2[off + e];
                float4 v3 = s3[off + e];
                int base = (e >> 3) * 32 + (e & 7) * 4;   // tc*32 + k0
                dst[base + 0] = make_ulonglong2(pk(v0.x, v1.x), pk(v2.x, v3.x));
                dst[base + 1] = make_ulonglong2(pk(v0.y, v1.y), pk(v2.y, v3.y));
                dst[base + 2] = make_ulonglong2(pk(v0.z, v1.z), pk(v2.z, v3.z));
                dst[base + 3] = make_ulonglong2(pk(v0.w, v1.w), pk(v2.w, v3.w));
            }
        };
        // reduce chunk c: lane = tc(0..7) + 8*kg; kg sums 8 k's, shfl tree over kg
        auto reduce = [&](int c) {
            const ulonglong2* pq = pbuf[pair][c & 1];
            const int tc = l & 7, kg = l >> 3;
            ull aA = z, aB = z;
            #pragma unroll
            for (int j = 0; j < 8; j++) {
                ulonglong2 v = pq[(kg * 8 + j) * (CK + 1) + tc];
                aA = add2(aA, v.x);
                aB = add2(aB, v.y);
            }
            aA = add2(aA, __shfl_xor_sync(0xffffffffu, aA, 8));
            aB = add2(aB, __shfl_xor_sync(0xffffffffu, aB, 8));
            aA = add2(aA, __shfl_xor_sync(0xffffffffu, aA, 16));
            aB = add2(aB, __shfl_xor_sync(0xffffffffu, aB, 16));
            if (kg == 0) {
                float2 fA = upk(aA), fB = upk(aB);
                const int t = c * CK + tc;
                out[(size_t)(b0 + 0) * TT + t] = fA.x + bo;
                out[(size_t)(b0 + 1) * TT + t] = fA.y + bo;
                out[(size_t)(b0 + 2) * TT + t] = fB.x + bo;
                out[(size_t)(b0 + 3) * TT + t] = fB.y + bo;
            }
        };

        loadx(0);
        for (int c = 0; c < NC; c++) {
            pair_bar(pair);                        // publish xb[c&1]
            if (c + 1 < NC) loadx(c + 1);
            if (c > 0) reduce(c - 1);
        }
        pair_bar(pair);
        reduce(NC - 1);
    }
    #undef CK
    #undef NC
}

extern "C" void kernel_launch(void* const* d_in, const int* in_sizes, int n_in,
                              void* d_out, int out_size) {
    const float* x     = (const float*)d_in[0];
    const float* h0    = (const float*)d_in[1];
    const float* W_ih  = (const float*)d_in[2];
    const float* b_ih  = (const float*)d_in[3];
    const float* W_hh  = (const float*)d_in[4];
    const float* b_hh  = (const float*)d_in[5];
    const float* W_out = (const float*)d_in[6];
    const float* b_out = (const float*)d_in[7];
    float* out = (float*)d_out;

    xproj_kernel<<<(BB * TT) / 512, 256>>>(x, W_ih, b_ih, b_hh);

    int wh = (out_size >= BB * TT + BB * HH) ? 1 : 0;
    rnn_kernel<<<BB / 8, 128>>>(h0, W_hh, W_out, b_out, out, wh);
}

// round 14
// speedup vs baseline: 1.4213x; 1.4213x over previous
#include <cuda_runtime.h>
#include <cstdint>

#define BB 1024
#define TT 512
#define II 64
#define HH 32

typedef unsigned long long ull;

// Scratch: x_proj with b_ih+b_hh folded in, layout [b][t][k]  (64 MB)
__device__ float g_xp[(size_t)BB * TT * HH];

// ---------- packed f32x2 helpers ----------
__device__ __forceinline__ ull pk(float lo, float hi) {
    ull r; asm("mov.b64 %0, {%1,%2};" : "=l"(r) : "f"(lo), "f"(hi)); return r;
}
__device__ __forceinline__ float2 upk(ull v) {
    float2 f; asm("mov.b64 {%0,%1}, %2;" : "=f"(f.x), "=f"(f.y) : "l"(v)); return f;
}
__device__ __forceinline__ ull fma2(ull a, ull b, ull c) {
    ull d; asm("fma.rn.f32x2 %0, %1, %2, %3;" : "=l"(d) : "l"(a), "l"(b), "l"(c)); return d;
}
__device__ __forceinline__ ull mul2(ull a, ull b) {
    ull d; asm("mul.rn.f32x2 %0, %1, %2;" : "=l"(d) : "l"(a), "l"(b)); return d;
}
__device__ __forceinline__ ull add2(ull a, ull b) {
    ull d; asm("add.rn.f32x2 %0, %1, %2;" : "=l"(d) : "l"(a), "l"(b)); return d;
}

// Hardware tanh approximation (MUFU.TANH, sm_75+): 1 op, lat ~16.
__device__ __forceinline__ float ftanh(float x) {
    float y; asm("tanh.approx.f32 %0, %1;" : "=f"(y) : "f"(x)); return y;
}

__device__ __forceinline__ void pair_bar(int pairid) {
    asm volatile("bar.sync %0, 64;" :: "r"(pairid + 1) : "memory");
}

// =====================================================================
// Kernel 1: x_proj (register-direct, double-buffered x prefetch).
// 256 threads/block (2 warps per SMSP for latency overlap), 2 rows/thread.
// (unchanged from the 168us-total round)
// =====================================================================
__global__ __launch_bounds__(256) void xproj_kernel(
    const float* __restrict__ x, const float* __restrict__ W_ih,
    const float* __restrict__ b_ih, const float* __restrict__ b_hh)
{
    __shared__ ull wT[II * 16];      // [i][kp] = {W[2kp][i], W[2kp+1][i]}   8 KB
    __shared__ ull bias2[16];
    const int tid = threadIdx.x;

    #pragma unroll
    for (int r = 0; r < 4; r++) {
        int e = tid + r * 256;                 // e = i*16 + kp
        int i = e >> 4, kp = e & 15;
        wT[e] = pk(W_ih[(2 * kp) * II + i], W_ih[(2 * kp + 1) * II + i]);
    }
    if (tid < 16)
        bias2[tid] = pk(b_ih[2 * tid] + b_hh[2 * tid],
                        b_ih[2 * tid + 1] + b_hh[2 * tid + 1]);
    __syncthreads();

    const size_t row0 = (size_t)blockIdx.x * 512 + tid * 2;
    const float4* xr0 = (const float4*)(x + row0 * II);
    const float4* xr1 = (const float4*)(x + (row0 + 1) * II);

    ull acc0[16], acc1[16];
    #pragma unroll
    for (int kp = 0; kp < 16; kp++) { ull b = bias2[kp]; acc0[kp] = b; acc1[kp] = b; }

    float4 bufA[2][4], bufB[2][4];
    #pragma unroll
    for (int u = 0; u < 4; u++) { bufA[0][u] = xr0[u]; bufB[0][u] = xr1[u]; }

    #pragma unroll
    for (int ic = 0; ic < 4; ic++) {
        const int cu = ic & 1;
        if (ic < 3) {
            #pragma unroll
            for (int u = 0; u < 4; u++) {
                bufA[cu ^ 1][u] = xr0[(ic + 1) * 4 + u];
                bufB[cu ^ 1][u] = xr1[(ic + 1) * 4 + u];
            }
        }
        const float* fa = (const float*)bufA[cu];
        const float* fb = (const float*)bufB[cu];
        #pragma unroll
        for (int ii = 0; ii < 16; ii++) {
            const int i = ic * 16 + ii;
            const ull xd0 = pk(fa[ii], fa[ii]);
            const ull xd1 = pk(fb[ii], fb[ii]);
            const ulonglong2* wrow = (const ulonglong2*)(wT + i * 16);
            #pragma unroll
            for (int kq = 0; kq < 8; kq++) {
                ulonglong2 w2 = wrow[kq];      // broadcast LDS.128
                acc0[2 * kq]     = fma2(w2.x, xd0, acc0[2 * kq]);
                acc0[2 * kq + 1] = fma2(w2.y, xd0, acc0[2 * kq + 1]);
                acc1[2 * kq]     = fma2(w2.x, xd1, acc1[2 * kq]);
                acc1[2 * kq + 1] = fma2(w2.y, xd1, acc1[2 * kq + 1]);
            }
        }
    }

    ulonglong2* o0 = (ulonglong2*)(g_xp + row0 * HH);
    ulonglong2* o1 = (ulonglong2*)(g_xp + (row0 + 1) * HH);
    #pragma unroll
    for (int kq = 0; kq < 8; kq++) {
        o0[kq] = make_ulonglong2(acc0[2 * kq], acc0[2 * kq + 1]);
        o1[kq] = make_ulonglong2(acc1[2 * kq], acc1[2 * kq + 1]);
    }
}

// =====================================================================
// Kernel 2: recurrence. 256-thread blocks = 4 producer/consumer pairs
// (producers = warps 0-3, one per SMSP; consumers = warps 4-7).
// Pair p: batches (blockIdx*8 + 2p, +2p+1), ONE packed f32x2 chain/warp.
// Changes vs 83us version: MUFU tanh.approx; next-x LDS + pbuf STS issued
// in the syncwarp shadow.
// =====================================================================
__global__ __launch_bounds__(256) void rnn_kernel(
    const float* __restrict__ h0, const float* __restrict__ W_hh,
    const float* __restrict__ W_out, const float* __restrict__ b_out,
    float* __restrict__ out, int write_hlast)
{
    #define CK 8
    #define NC (TT / CK)               // 64 chunks
    __shared__ ull xb[4][2][CK * 32];         // [pair][par][tc*32 + k] = {xp_b0, xp_b1}
    __shared__ ull pbuf[4][2][32 * (CK + 1)]; // [pair][par][k*9 + tc] = wo_k * h2
    __shared__ ull hbuf[4][2][HH];            // [pair][phase][k]

    const int wid  = threadIdx.x >> 5;
    const int lane = threadIdx.x & 31;
    const int pair = wid & 3;
    const int b0 = blockIdx.x * 8 + pair * 2;
    const ull z = pk(0.0f, 0.0f);

    if (wid < 4) {
        // ---------------- producer warp (one per SMSP) ----------------
        const int k = lane;
        ull wp2[HH];
        #pragma unroll
        for (int j = 0; j < HH; j++) { float w = W_hh[k * HH + j]; wp2[j] = pk(w, w); }
        const float wo = W_out[k];
        const ull wop = pk(wo, wo);

        float hA = h0[b0 * HH + k];
        float hB = h0[(b0 + 1) * HH + k];
        hbuf[pair][0][k] = pk(hA, hB);

        for (int c = 0; c < NC; c++) {
            pair_bar(pair);                    // xb[pair][c&1] ready, pbuf[c&1] free
            const ull* xq = xb[pair][c & 1];
            ull* pq = pbuf[pair][c & 1];
            ull xv = xq[k];                    // step-0 x
            #pragma unroll
            for (int tc = 0; tc < CK; tc++) {
                const int ph = tc & 1;
                ull a0 = xv;
                ull a1 = z, a2 = z, a3 = z, a4 = z, a5 = z, a6 = z, a7 = z;
                const ulonglong2* hb2 = (const ulonglong2*)hbuf[pair][ph];
                #pragma unroll
                for (int m = 0; m < 16; m += 4) {
                    ulonglong2 h0v = hb2[m];
                    a0 = fma2(wp2[2 * m    ], h0v.x, a0);
                    a1 = fma2(wp2[2 * m + 1], h0v.y, a1);
                    ulonglong2 h1v = hb2[m + 1];
                    a2 = fma2(wp2[2 * m + 2], h1v.x, a2);
                    a3 = fma2(wp2[2 * m + 3], h1v.y, a3);
                    ulonglong2 h2v = hb2[m + 2];
                    a4 = fma2(wp2[2 * m + 4], h2v.x, a4);
                    a5 = fma2(wp2[2 * m + 5], h2v.y, a5);
                    ulonglong2 h3v = hb2[m + 3];
                    a6 = fma2(wp2[2 * m + 6], h3v.x, a6);
                    a7 = fma2(wp2[2 * m + 7], h3v.y, a7);
                }
                ull t0 = add2(a0, a4), t1 = add2(a1, a5);
                ull t2 = add2(a2, a6), t3 = add2(a3, a7);
                ull s = add2(add2(t0, t2), add2(t1, t3));
                float2 f = upk(s);
                hA = ftanh(f.x); hB = ftanh(f.y);       // 2x MUFU.TANH
                ull h2 = pk(hA, hB);
                hbuf[pair][ph ^ 1][k] = h2;             // STS (critical)
                // shadow work while the STS drains toward the syncwarp:
                ull xn = (tc + 1 < CK) ? xq[(tc + 1) * 32 + k] : xv;  // next x LDS
                pq[k * (CK + 1) + tc] = mul2(wop, h2);  // off-chain product
                __syncwarp();
                xv = xn;
            }
        }
        pair_bar(pair);                        // final pbuf chunk visible
        if (write_hlast) {
            float* hl = out + (size_t)BB * TT;
            hl[b0 * HH + k] = hA;
            hl[(b0 + 1) * HH + k] = hB;
        }
    } else {
        // ---------------- consumer warp ----------------
        const int l = lane;
        const float bo = b_out[0];
        const float4* src0 = (const float4*)(g_xp + (size_t)b0 * TT * HH);
        const float4* src1 = src0 + (TT * HH) / 4;

        // chunk loader: 2 KB -> xb[pair][par], packed f32x2 {b0,b1}
        auto loadx = [&](int c) {
            const float4* s0 = src0 + c * (CK * HH / 4);
            const float4* s1 = src1 + c * (CK * HH / 4);
            ulonglong2* dst = (ulonglong2*)xb[pair][c & 1];
            #pragma unroll
            for (int u = 0; u < 2; u++) {
                int e = u * 32 + l;            // float4 index 0..63
                float4 a = s0[e];
                float4 b = s1[e];
                int tc = e >> 3, kq = e & 7;
                dst[tc * 16 + kq * 2    ] = make_ulonglong2(pk(a.x, b.x), pk(a.y, b.y));
                dst[tc * 16 + kq * 2 + 1] = make_ulonglong2(pk(a.z, b.z), pk(a.w, b.w));
            }
        };
        // reduce chunk c: lane = tc + 8*kg; kg sums 8 k values, then shfl tree
        auto reduce = [&](int c) {
            const ull* pq = pbuf[pair][c & 1];
            const int tc = l & 7, kg = l >> 3;
            ull a0 = z, a1 = z;
            #pragma unroll
            for (int j = 0; j < 8; j += 2) {
                a0 = add2(a0, pq[(kg * 8 + j    ) * (CK + 1) + tc]);
                a1 = add2(a1, pq[(kg * 8 + j + 1) * (CK + 1) + tc]);
            }
            ull a = add2(a0, a1);
            a = add2(a, __shfl_xor_sync(0xffffffffu, a, 8));
            a = add2(a, __shfl_xor_sync(0xffffffffu, a, 16));
            if (kg == 0) {
                float2 f = upk(a);
                out[(size_t)b0 * TT + c * CK + tc]       = f.x + bo;
                out[(size_t)(b0 + 1) * TT + c * CK + tc] = f.y + bo;
            }
        };

        loadx(0);
        for (int c = 0; c < NC; c++) {
            pair_bar(pair);                    // publish xb[c&1]
            if (c + 1 < NC) loadx(c + 1);
            if (c > 0) reduce(c - 1);
        }
        pair_bar(pair);
        reduce(NC - 1);
    }
    #undef CK
    #undef NC
}

extern "C" void kernel_launch(void* const* d_in, const int* in_sizes, int n_in,
                              void* d_out, int out_size) {
    const float* x     = (const float*)d_in[0];
    const float* h0    = (const float*)d_in[1];
    const float* W_ih  = (const float*)d_in[2];
    const float* b_ih  = (const float*)d_in[3];
    const float* W_hh  = (const float*)d_in[4];
    const float* b_hh  = (const float*)d_in[5];
    const float* W_out = (const float*)d_in[6];
    const float* b_out = (const float*)d_in[7];
    float* out = (float*)d_out;

    xproj_kernel<<<(BB * TT) / 512, 256>>>(x, W_ih, b_ih, b_hh);

    int wh = (out_size >= BB * TT + BB * HH) ? 1 : 0;
    rnn_kernel<<<BB / 8, 256>>>(h0, W_hh, W_out, b_out, out, wh);
}